// round 9
// baseline (speedup 1.0000x reference)
#include <cuda_runtime.h>
#include <cuda_bf16.h>
#include <math.h>
#include <stdint.h>

#define B_ 8
#define T_ 2048
#define C_ 1024
#define H_ 64
#define NROW (B_*T_)

// Projected q,k,v as bf16 hi/lo pairs
__device__ __nv_bfloat16 g_qh[NROW*H_], g_ql[NROW*H_];
__device__ __nv_bfloat16 g_kh[NROW*H_], g_kl[NROW*H_];
__device__ __nv_bfloat16 g_vh[NROW*H_], g_vl[NROW*H_];
// W transposed to [192 cols][1024 k] bf16 hi/lo (ldsm-ready)
__device__ __nv_bfloat16 g_wth[192*1024], g_wtl[192*1024];
// attention partials: [b][tt(16)][ch(8)][128r][64h] / [b][tt][ch][128r]
__device__ float scr_o[8*16*8*128*64];
__device__ float scr_l[8*16*8*128];

// ---------------------------------------------------------------------------
__device__ __forceinline__ uint32_t smem_u32(const void* p) {
    uint32_t a;
    asm("{ .reg .u64 t; cvta.to.shared.u64 t, %1; cvt.u32.u64 %0, t; }" : "=r"(a) : "l"(p));
    return a;
}
__device__ __forceinline__ void ldsm_x4(uint32_t* r, uint32_t addr) {
    asm volatile("ldmatrix.sync.aligned.m8n8.x4.shared.b16 {%0,%1,%2,%3}, [%4];"
                 : "=r"(r[0]), "=r"(r[1]), "=r"(r[2]), "=r"(r[3]) : "r"(addr));
}
__device__ __forceinline__ void ldsm_x4_t(uint32_t* r, uint32_t addr) {
    asm volatile("ldmatrix.sync.aligned.m8n8.x4.trans.shared.b16 {%0,%1,%2,%3}, [%4];"
                 : "=r"(r[0]), "=r"(r[1]), "=r"(r[2]), "=r"(r[3]) : "r"(addr));
}
__device__ __forceinline__ void mma16816(float* d, const uint32_t* a, uint32_t b0, uint32_t b1) {
    asm volatile(
        "mma.sync.aligned.m16n8k16.row.col.f32.bf16.bf16.f32 "
        "{%0,%1,%2,%3}, {%4,%5,%6,%7}, {%8,%9}, {%0,%1,%2,%3};"
        : "+f"(d[0]), "+f"(d[1]), "+f"(d[2]), "+f"(d[3])
        : "r"(a[0]), "r"(a[1]), "r"(a[2]), "r"(a[3]), "r"(b0), "r"(b1));
}
__device__ __forceinline__ uint32_t pack_bf16(float a, float b) {
    __nv_bfloat16 ha = __float2bfloat16(a), hb = __float2bfloat16(b);
    return (uint32_t)*(uint16_t*)&ha | ((uint32_t)*(uint16_t*)&hb << 16);
}
__device__ __forceinline__ float bf16hi_f(float x) {
    return __bfloat162float(__float2bfloat16(x));
}
#define CP_ASYNC16(dst, src) \
    asm volatile("cp.async.cg.shared.global [%0], [%1], 16;" :: "r"(dst), "l"(src))
#define CP_COMMIT() asm volatile("cp.async.commit_group;" ::: "memory")
#define CP_WAIT(n)  asm volatile("cp.async.wait_group %0;" :: "n"(n) : "memory")

// ---------------------------------------------------------------------------
// Kernel 0: transpose W -> [192][1024] bf16 hi/lo
// ---------------------------------------------------------------------------
__global__ __launch_bounds__(256) void wprep(
    const float* __restrict__ Wq, const float* __restrict__ Wk, const float* __restrict__ Wv)
{
    __shared__ float s[64][65];
    const int m  = blockIdx.x >> 4;
    const int k0 = (blockIdx.x & 15) * 64;
    const float* W = (m == 0) ? Wq : ((m == 1) ? Wk : Wv);
    const int tid = threadIdx.x;

#pragma unroll
    for (int i = 0; i < 16; i++) {
        int idx = tid + i * 256;
        int kk = idx >> 6, n = idx & 63;
        s[kk][n] = W[(size_t)(k0 + kk) * H_ + n];
    }
    __syncthreads();
#pragma unroll
    for (int i = 0; i < 8; i++) {
        int idx = tid + i * 256;
        int n = idx >> 5, kp = idx & 31;
        float a = s[2 * kp][n], b = s[2 * kp + 1][n];
        size_t off = (size_t)(m * 64 + n) * 1024 + k0 + 2 * kp;
        *(uint32_t*)&g_wth[off] = pack_bf16(a, b);
        *(uint32_t*)&g_wtl[off] = pack_bf16(a - bf16hi_f(a), b - bf16hi_f(b));
    }
}

// ---------------------------------------------------------------------------
// Kernel 1: QKV projection, mma.sync bf16 hi/lo split (unchanged from R8).
// ---------------------------------------------------------------------------
#define KC 32
#define ASZ (128*80)
#define BSZ (192*80)
#define STG_SZ (2*ASZ + 2*BSZ)
#define QKV_SMEM (2*STG_SZ)

__global__ __launch_bounds__(512, 1) void qkv_mma(const float* __restrict__ x)
{
    extern __shared__ char smem[];
    const uint32_t sb = smem_u32(smem);
    const int tid  = threadIdx.x;
    const int wid  = tid >> 5, lane = tid & 31;
    const int wm   = wid >> 2, wn = wid & 3;
    const int m0   = blockIdx.x * 128;

    float d[2][6][4];
#pragma unroll
    for (int i = 0; i < 2; i++)
#pragma unroll
        for (int j = 0; j < 6; j++)
#pragma unroll
            for (int e = 0; e < 4; e++) d[i][j][e] = 0.f;

    const int ar  = tid >> 3;
    const int ac4 = (tid & 7) * 4;

    {
        char* base = smem;
#pragma unroll
        for (int i = 0; i < 2; i++) {
            int r = ar + i * 64;
            float4 v = *(const float4*)&x[(size_t)(m0 + r) * C_ + ac4];
            float h0 = bf16hi_f(v.x), h1 = bf16hi_f(v.y), h2 = bf16hi_f(v.z), h3 = bf16hi_f(v.w);
            uint32_t off = (uint32_t)(r * 80 + ac4 * 2);
            *(uint2*)(base + off)       = make_uint2(pack_bf16(v.x, v.y), pack_bf16(v.z, v.w));
            *(uint2*)(base + ASZ + off) = make_uint2(pack_bf16(v.x - h0, v.y - h1), pack_bf16(v.z - h2, v.w - h3));
        }
#pragma unroll
        for (int i = 0; i < 3; i++) {
            int idx = tid + i * 512;
            int hl = idx >= 768;
            int j  = idx - hl * 768;
            int row = j >> 2, seg = j & 3;
            const __nv_bfloat16* src = (hl ? g_wtl : g_wth) + (size_t)row * 1024 + seg * 8;
            CP_ASYNC16(sb + 2 * ASZ + hl * BSZ + row * 80 + seg * 16, src);
        }
        CP_COMMIT();
    }

    const uint32_t a_l = (uint32_t)((wm * 32 + (lane & 15)) * 80 + ((lane >> 4) * 8) * 2);
    const uint32_t b_l = (uint32_t)((wn * 48 + (lane & 7) + ((lane >> 4) << 3)) * 80
                                    + (((lane >> 3) & 1) * 8) * 2);

    for (int c = 0; c < 32; c++) {
        const int s = c & 1;
        CP_WAIT(0);
        __syncthreads();

        float4 av[2];
        if (c < 31) {
            const int k0 = (c + 1) * KC;
#pragma unroll
            for (int i = 0; i < 2; i++)
                av[i] = *(const float4*)&x[(size_t)(m0 + ar + i * 64) * C_ + k0 + ac4];
            const uint32_t dst0 = sb + (s ^ 1) * STG_SZ + 2 * ASZ;
#pragma unroll
            for (int i = 0; i < 3; i++) {
                int idx = tid + i * 512;
                int hl = idx >= 768;
                int j  = idx - hl * 768;
                int row = j >> 2, seg = j & 3;
                const __nv_bfloat16* src = (hl ? g_wtl : g_wth) + (size_t)row * 1024 + k0 + seg * 8;
                CP_ASYNC16(dst0 + hl * BSZ + row * 80 + seg * 16, src);
            }
            CP_COMMIT();
        }

        const uint32_t abase = sb + s * STG_SZ;
        const uint32_t bbase = abase + 2 * ASZ;
#pragma unroll
        for (int ks = 0; ks < 2; ks++) {
            uint32_t ah[2][4], al[2][4];
#pragma unroll
            for (int mt = 0; mt < 2; mt++) {
                uint32_t ad = abase + a_l + (uint32_t)(mt * 16 * 80 + ks * 32);
                ldsm_x4(ah[mt], ad);
                ldsm_x4(al[mt], ad + ASZ);
            }
#pragma unroll
            for (int ng = 0; ng < 3; ng++) {
                uint32_t bh[4], bl[4];
                uint32_t bd = bbase + b_l + (uint32_t)(ng * 16 * 80 + ks * 32);
                ldsm_x4(bh, bd);
                ldsm_x4(bl, bd + BSZ);
#pragma unroll
                for (int mt = 0; mt < 2; mt++) {
                    mma16816(d[mt][ng * 2],     ah[mt], bh[0], bh[1]);
                    mma16816(d[mt][ng * 2 + 1], ah[mt], bh[2], bh[3]);
                    mma16816(d[mt][ng * 2],     ah[mt], bl[0], bl[1]);
                    mma16816(d[mt][ng * 2 + 1], ah[mt], bl[2], bl[3]);
                    mma16816(d[mt][ng * 2],     al[mt], bh[0], bh[1]);
                    mma16816(d[mt][ng * 2 + 1], al[mt], bh[2], bh[3]);
                }
            }
        }

        if (c < 31) {
            char* base = smem + (s ^ 1) * STG_SZ;
#pragma unroll
            for (int i = 0; i < 2; i++) {
                int r = ar + i * 64;
                float4 v = av[i];
                float h0 = bf16hi_f(v.x), h1 = bf16hi_f(v.y), h2 = bf16hi_f(v.z), h3 = bf16hi_f(v.w);
                uint32_t off = (uint32_t)(r * 80 + ac4 * 2);
                *(uint2*)(base + off)       = make_uint2(pack_bf16(v.x, v.y), pack_bf16(v.z, v.w));
                *(uint2*)(base + ASZ + off) = make_uint2(pack_bf16(v.x - h0, v.y - h1), pack_bf16(v.z - h2, v.w - h3));
            }
        }
        __syncthreads();
    }

    __nv_bfloat16* const ghi[3] = {g_qh, g_kh, g_vh};
    __nv_bfloat16* const glo[3] = {g_ql, g_kl, g_vl};
    const int gid = lane >> 2, tig = lane & 3;
#pragma unroll
    for (int mt = 0; mt < 2; mt++) {
#pragma unroll
        for (int nt = 0; nt < 6; nt++) {
            int colb  = wn * 48 + nt * 8;
            int mtx   = colb >> 6;
            int colin = (colb & 63) + tig * 2;
            int row   = m0 + wm * 32 + mt * 16 + gid;
            float v0 = d[mt][nt][0], v1 = d[mt][nt][1];
            float v2 = d[mt][nt][2], v3 = d[mt][nt][3];
            size_t o0 = (size_t)row * H_ + colin, o1 = (size_t)(row + 8) * H_ + colin;
            *(uint32_t*)&ghi[mtx][o0] = pack_bf16(v0, v1);
            *(uint32_t*)&glo[mtx][o0] = pack_bf16(v0 - bf16hi_f(v0), v1 - bf16hi_f(v1));
            *(uint32_t*)&ghi[mtx][o1] = pack_bf16(v2, v3);
            *(uint32_t*)&glo[mtx][o1] = pack_bf16(v2 - bf16hi_f(v2), v3 - bf16hi_f(v3));
        }
    }
}

// ---------------------------------------------------------------------------
// Kernel 2: attention partials, q-tile = 128 rows, chunk = 4 s-tiles.
// Each warp owns 32 q-rows (2 m16 tiles). Per-warp skip of fully-masked
// diagonal tiles (no barriers inside skipped region).
// 72 (tt,ch) units x 8 batches = 576 CTAs.
// ---------------------------------------------------------------------------
#define TSTR 144
#define TILE (64*TSTR)            // 9216
#define QTILE (128*TSTR)          // 18432
#define ATT_SMEM (2*QTILE + 2*4*TILE)   // 110592

__global__ __launch_bounds__(128) void attn_part(const float* __restrict__ rbias)
{
    extern __shared__ char smem[];
    const uint32_t sb = smem_u32(smem);
    const int tid  = threadIdx.x;
    const int wq   = tid >> 5;
    const int lane = tid & 31;
    const int gid  = lane >> 2, tig = lane & 3;

    const int b = blockIdx.x & 7;
    int u = 71 - (blockIdx.x >> 3);              // big work first
    int tt = 0;
    {
        int cum = 0;
        while (cum + ((tt + 2) >> 1) <= u) { cum += (tt + 2) >> 1; tt++; }
        u -= cum;                                 // u is now ch
    }
    const int ch   = u;
    const int sbeg = ch * 4;
    const int send = min(sbeg + 4, 2 * tt + 2);
    const int t0   = tt * 128;

    const size_t rowbase = (size_t)b * T_;
    const float inv_sqrt_c = 0.03125f;

    const uint32_t QH = sb, QL = sb + QTILE;
    const uint32_t BUF = sb + 2 * QTILE;

    const uint32_t b_off = (uint32_t)(((lane & 7) + ((lane >> 4) << 3)) * TSTR + (((lane >> 3) & 1) * 8) * 2);
    const uint32_t v_off = (uint32_t)(((lane & 7) + (((lane >> 3) & 1) << 3)) * TSTR + ((lane >> 4) * 8) * 2);

    // q tile hi/lo: 128 rows
#pragma unroll
    for (int i = 0; i < 8; i++) {
        int idx = tid + i * 128;
        int c = idx >> 3, chh = idx & 7;
        size_t go = (rowbase + t0 + c) * H_ + chh * 8;
        uint32_t so = (uint32_t)(c * TSTR + chh * 16);
        *(uint4*)(smem + so)         = *(const uint4*)&g_qh[go];
        *(uint4*)(smem + QTILE + so) = *(const uint4*)&g_ql[go];
    }

    // first s-tile -> buf0
    {
        const __nv_bfloat16* srcs[4] = {g_kh, g_kl, g_vh, g_vl};
#pragma unroll
        for (int t = 0; t < 4; t++) {
            const __nv_bfloat16* g = srcs[t] + (rowbase + sbeg * 64) * H_;
            uint32_t db = BUF + t * TILE;
#pragma unroll
            for (int i = 0; i < 4; i++) {
                int idx = tid + i * 128;
                int c = idx >> 3, chh = idx & 7;
                CP_ASYNC16(db + c * TSTR + chh * 16, g + (size_t)c * H_ + chh * 8);
            }
        }
        CP_COMMIT();
    }

    float o[2][8][4];
    float l[2][2];
#pragma unroll
    for (int mt = 0; mt < 2; mt++) {
        l[mt][0] = l[mt][1] = 0.f;
#pragma unroll
        for (int j = 0; j < 8; j++)
#pragma unroll
            for (int e = 0; e < 4; e++) o[mt][j][e] = 0.f;
    }

    const int wrow_max = t0 + wq * 32 + 31;       // warp's highest q row

    for (int st = sbeg; st < send; st++) {
        const int s0 = st * 64;
        __syncthreads();

        if (st < send - 1) {
            const __nv_bfloat16* srcs[4] = {g_kh, g_kl, g_vh, g_vl};
            uint32_t dbase = BUF + ((st + 1 - sbeg) & 1) * (4 * TILE);
#pragma unroll
            for (int t = 0; t < 4; t++) {
                const __nv_bfloat16* g = srcs[t] + (rowbase + (st + 1) * 64) * H_;
                uint32_t db = dbase + t * TILE;
#pragma unroll
                for (int i = 0; i < 4; i++) {
                    int idx = tid + i * 128;
                    int c = idx >> 3, chh = idx & 7;
                    CP_ASYNC16(db + c * TSTR + chh * 16, g + (size_t)c * H_ + chh * 8);
                }
            }
            CP_COMMIT();
            CP_WAIT(1);
        } else {
            CP_WAIT(0);
        }
        __syncthreads();

        if (s0 > wrow_max) continue;              // whole tile masked for this warp

        const uint32_t khb = BUF + ((st - sbeg) & 1) * (4 * TILE);
        const uint32_t klb = khb + TILE, vhb = khb + 2 * TILE, vlb = khb + 3 * TILE;

        // ---- S = Q K^T for both m-tiles ----
        float p[2][8][4];
#pragma unroll
        for (int mt = 0; mt < 2; mt++)
#pragma unroll
            for (int j = 0; j < 8; j++)
#pragma unroll
                for (int e = 0; e < 4; e++) p[mt][j][e] = 0.f;

#pragma unroll
        for (int kk = 0; kk < 4; kk++) {
            uint32_t ah[2][4], al[2][4];
#pragma unroll
            for (int mt = 0; mt < 2; mt++) {
                uint32_t ad = (uint32_t)((wq * 32 + mt * 16 + (lane & 15)) * TSTR
                                         + ((lane >> 4) * 8) * 2 + kk * 32);
                ldsm_x4(ah[mt], QH + ad);
                ldsm_x4(al[mt], QL + ad);
            }
#pragma unroll
            for (int nj = 0; nj < 4; nj++) {
                uint32_t bh[4], bl[4];
                uint32_t bo = b_off + (uint32_t)(nj * 16 * TSTR + kk * 32);
                ldsm_x4(bh, khb + bo);
                ldsm_x4(bl, klb + bo);
#pragma unroll
                for (int mt = 0; mt < 2; mt++) {
                    mma16816(p[mt][nj*2],   ah[mt], bh[0], bh[1]);
                    mma16816(p[mt][nj*2+1], ah[mt], bh[2], bh[3]);
                    mma16816(p[mt][nj*2],   ah[mt], bl[0], bl[1]);
                    mma16816(p[mt][nj*2+1], ah[mt], bl[2], bl[3]);
                    mma16816(p[mt][nj*2],   al[mt], bh[0], bh[1]);
                    mma16816(p[mt][nj*2+1], al[mt], bh[2], bh[3]);
                }
            }
        }

        // ---- bias + mask + exp (shift-free) ----
#pragma unroll
        for (int mt = 0; mt < 2; mt++) {
            const int r0 = t0 + wq * 32 + mt * 16 + gid;
            const int r1 = r0 + 8;
#pragma unroll
            for (int j = 0; j < 8; j++) {
                const int col = s0 + j * 8 + tig * 2;
                float2 rb0 = *(const float2*)&rbias[(size_t)r0 * T_ + col];
                float2 rb1 = *(const float2*)&rbias[(size_t)r1 * T_ + col];
                bool ok00 = (col     <= r0) && ((rb0.x > 0.f) || (col     == r0));
                bool ok01 = (col + 1 <= r0) && ((rb0.y > 0.f) || (col + 1 == r0));
                bool ok10 = (col     <= r1) && ((rb1.x > 0.f) || (col     == r1));
                bool ok11 = (col + 1 <= r1) && ((rb1.y > 0.f) || (col + 1 == r1));
                p[mt][j][0] = ok00 ? __expf(fmaf(p[mt][j][0], inv_sqrt_c, rb0.x)) : 0.f;
                p[mt][j][1] = ok01 ? __expf(fmaf(p[mt][j][1], inv_sqrt_c, rb0.y)) : 0.f;
                p[mt][j][2] = ok10 ? __expf(fmaf(p[mt][j][2], inv_sqrt_c, rb1.x)) : 0.f;
                p[mt][j][3] = ok11 ? __expf(fmaf(p[mt][j][3], inv_sqrt_c, rb1.y)) : 0.f;
                l[mt][0] += p[mt][j][0] + p[mt][j][1];
                l[mt][1] += p[mt][j][2] + p[mt][j][3];
            }
        }

        // ---- O += P V (V ldsm'd once, applied to both m-tiles) ----
#pragma unroll
        for (int sj = 0; sj < 4; sj++) {
            uint32_t phf[2][4], plf[2][4];
#pragma unroll
            for (int mt = 0; mt < 2; mt++) {
                const float* pa = p[mt][2*sj];
                const float* pb = p[mt][2*sj+1];
                phf[mt][0] = pack_bf16(pa[0], pa[1]);
                phf[mt][1] = pack_bf16(pa[2], pa[3]);
                phf[mt][2] = pack_bf16(pb[0], pb[1]);
                phf[mt][3] = pack_bf16(pb[2], pb[3]);
                plf[mt][0] = pack_bf16(pa[0] - bf16hi_f(pa[0]), pa[1] - bf16hi_f(pa[1]));
                plf[mt][1] = pack_bf16(pa[2] - bf16hi_f(pa[2]), pa[3] - bf16hi_f(pa[3]));
                plf[mt][2] = pack_bf16(pb[0] - bf16hi_f(pb[0]), pb[1] - bf16hi_f(pb[1]));
                plf[mt][3] = pack_bf16(pb[2] - bf16hi_f(pb[2]), pb[3] - bf16hi_f(pb[3]));
            }
#pragma unroll
            for (int hj = 0; hj < 4; hj++) {
                uint32_t vh[4], vl[4];
                uint32_t vo = v_off + (uint32_t)(sj * 16 * TSTR + hj * 32);
                ldsm_x4_t(vh, vhb + vo);
                ldsm_x4_t(vl, vlb + vo);
#pragma unroll
                for (int mt = 0; mt < 2; mt++) {
                    mma16816(o[mt][hj*2],   phf[mt], vh[0], vh[1]);
                    mma16816(o[mt][hj*2+1], phf[mt], vh[2], vh[3]);
                    mma16816(o[mt][hj*2],   phf[mt], vl[0], vl[1]);
                    mma16816(o[mt][hj*2+1], phf[mt], vl[2], vl[3]);
                    mma16816(o[mt][hj*2],   plf[mt], vh[0], vh[1]);
                    mma16816(o[mt][hj*2+1], plf[mt], vh[2], vh[3]);
                }
            }
        }
    }

    // write partials
    float* po = scr_o + (size_t)((b * 16 + tt) * 8 + ch) * (128 * 64);
    float* pl = scr_l + (size_t)((b * 16 + tt) * 8 + ch) * 128;
#pragma unroll
    for (int mt = 0; mt < 2; mt++) {
        const int rw = wq * 32 + mt * 16 + gid;
#pragma unroll
        for (int j = 0; j < 8; j++) {
            int hcol = j * 8 + tig * 2;
            *(float2*)&po[rw * 64 + hcol]       = make_float2(o[mt][j][0], o[mt][j][1]);
            *(float2*)&po[(rw + 8) * 64 + hcol] = make_float2(o[mt][j][2], o[mt][j][3]);
        }
        float l0 = l[mt][0], l1 = l[mt][1];
        l0 += __shfl_xor_sync(0xffffffffu, l0, 1);
        l0 += __shfl_xor_sync(0xffffffffu, l0, 2);
        l1 += __shfl_xor_sync(0xffffffffu, l1, 1);
        l1 += __shfl_xor_sync(0xffffffffu, l1, 2);
        if (tig == 0) { pl[rw] = l0; pl[rw + 8] = l1; }
    }
}

// ---------------------------------------------------------------------------
// Kernel 3: vectorized fixed-order reduction + normalize.
// grid 512 = (b, tt, 32-row group), 256 threads, float4.
// ---------------------------------------------------------------------------
__global__ __launch_bounds__(256) void attn_reduce(float* __restrict__ out)
{
    const int b  = blockIdx.x >> 6;
    const int tt = (blockIdx.x >> 2) & 15;
    const int qr = blockIdx.x & 3;
    const int nch = (tt + 2) >> 1;
    const int tid = threadIdx.x;

    const float4* po = (const float4*)(scr_o + (size_t)(b * 16 + tt) * 8 * (128 * 64)) + qr * 512;
    const float*  pl = scr_l + (size_t)(b * 16 + tt) * 8 * 128 + qr * 32;
    float4* o4 = (float4*)out;

#pragma unroll
    for (int e = 0; e < 2; e++) {
        int idx = tid + e * 256;          // 512 float4 = 32 rows x 16
        int row = idx >> 4;
        float4 acc = make_float4(0.f, 0.f, 0.f, 0.f);
        float l = 0.f;
        for (int c = 0; c < nch; c++) {
            float4 v = po[c * 2048 + idx];
            acc.x += v.x; acc.y += v.y; acc.z += v.z; acc.w += v.w;
            l += pl[c * 128 + row];
        }
        float il = 1.0f / l;
        acc.x *= il; acc.y *= il; acc.z *= il; acc.w *= il;
        o4[((size_t)b * T_ + tt * 128 + qr * 32 + row) * 16 + (idx & 15)] = acc;
    }
}

// ---------------------------------------------------------------------------
extern "C" void kernel_launch(void* const* d_in, const int* in_sizes, int n_in,
                              void* d_out, int out_size)
{
    const float* x     = (const float*)d_in[0];
    const float* Wq    = (const float*)d_in[1];
    const float* Wk    = (const float*)d_in[2];
    const float* Wv    = (const float*)d_in[3];
    const float* rbias = (const float*)d_in[4];
    float* out = (float*)d_out;

    static bool attr_set = false;
    if (!attr_set) {
        cudaFuncSetAttribute(qkv_mma,   cudaFuncAttributeMaxDynamicSharedMemorySize, QKV_SMEM);
        cudaFuncSetAttribute(attn_part, cudaFuncAttributeMaxDynamicSharedMemorySize, ATT_SMEM);
        attr_set = true;
    }

    wprep<<<48, 256>>>(Wq, Wk, Wv);
    qkv_mma<<<NROW / 128, 512, QKV_SMEM>>>(x);
    attn_part<<<72 * B_, 128, ATT_SMEM>>>(rbias);
    attn_reduce<<<512, 256>>>(out);
}